// round 8
// baseline (speedup 1.0000x reference)
#include <cuda_runtime.h>
#include <cuda_bf16.h>
#include <cstdint>

#define B_ 4
#define T_ 2048
#define H_ 16
#define D_ 128
#define HD 2048        // H_*D_
#define S_ 16          // steps per chunk
#define NC (T_/S_)     // 128 chunks

// smem (float offsets): q/f double-buffered via cp.async; kg/vg single-buffered.
// qf buffer b at b*5120: q tile at +0, f tile at +2560 (16 t * 160 floats each)
#define KG_OFF 10240   // kg rows: 16 t * 160
#define VG_OFF 12800   // vg cols: 16 t * 64
#define SM_FLOATS 13824
#define SM_BYTES  55296

typedef unsigned long long u64;

__device__ __forceinline__ u64 pk2(float x, float y) {
    u64 r; asm("mov.b64 %0,{%1,%2};" : "=l"(r) : "f"(x), "f"(y)); return r;
}
__device__ __forceinline__ float2 up2(u64 a) {
    float2 r; asm("mov.b64 {%0,%1},%2;" : "=f"(r.x), "=f"(r.y) : "l"(a)); return r;
}
__device__ __forceinline__ u64 mul2(u64 a, u64 b) {
    u64 d; asm("mul.rn.f32x2 %0,%1,%2;" : "=l"(d) : "l"(a), "l"(b)); return d;
}
__device__ __forceinline__ u64 add2(u64 a, u64 b) {
    u64 d; asm("add.rn.f32x2 %0,%1,%2;" : "=l"(d) : "l"(a), "l"(b)); return d;
}
__device__ __forceinline__ u64 fma2(u64 a, u64 b, u64 c) {
    u64 d; asm("fma.rn.f32x2 %0,%1,%2,%3;" : "=l"(d) : "l"(a), "l"(b), "l"(c)); return d;
}
__device__ __forceinline__ u64 max2c(u64 a, float c) {
    float2 t = up2(a);
    t.x = fmaxf(t.x, c); t.y = fmaxf(t.y, c);
    return pk2(t.x, t.y);
}
__device__ __forceinline__ void cp16(uint32_t dst, const float* src) {
    asm volatile("cp.async.cg.shared.global [%0], [%1], 16;" :: "r"(dst), "l"(src) : "memory");
}
__device__ __forceinline__ uint32_t s2u(const void* p) {
    uint32_t a;
    asm("{ .reg .u64 t; cvta.to.shared.u64 t, %1; cvt.u32.u64 %0, t; }" : "=r"(a) : "l"(p));
    return a;
}

// Row tile per t: 8 blocks of (16 floats + 4 pad) = 160 floats.
// Granule a (rows 4a..4a+3) at t*160 + (a>>2)*20 + (a&3)*4 -> conflict-free LDS.128.
__global__ __launch_bounds__(512, 1) void delta_kernel(
    const float* __restrict__ q, const float* __restrict__ k,
    const float* __restrict__ v, const float* __restrict__ f,
    const float* __restrict__ g, float* __restrict__ out)
{
    extern __shared__ float smp[];
    const uint32_t smem0 = s2u(smp);

    const int tid  = threadIdx.x;
    const int w    = tid >> 5, lane = tid & 31;
    const int r    = lane >> 2;          // 8 row-groups of 16 rows
    const int c    = lane & 3;           // 4 columns per warp
    const int colbase = blockIdx.x * 64;
    const long base0  = (long)blockIdx.z * T_ * HD + (long)blockIdx.y * D_;

    // staging roles (identical to R2): rows (t, 4-float granule); cols (t, 4-col block)
    const int  s_s = tid >> 5, s_rb = tid & 31;
    const int  c_s = tid >> 4, c_cb = tid & 15;
    const bool colth = (tid < 256);
    const long growb = base0 + (long)s_s * HD + s_rb * 4;
    const long gcolb = base0 + (long)c_s * HD + colbase + c_cb * 4;
    const int  rbidx = s_s * 160 + (s_rb >> 2) * 20 + (s_rb & 3) * 4;
    const uint32_t d_row = (uint32_t)rbidx * 4;     // byte offset of row granule

    // compute constants
    const int rl  = r * 20;
    const int dj  = colbase + w * 4 + c;
    const int fcidx = (dj >> 4) * 20 + (dj & 15);
    const int vcidx = w * 4 + c;
    float* outp = out + base0 + dj;

    // prime: cp.async q,f chunk 0 -> buffer 0; LDG k,g (+ v,gc) into regs
    cp16(smem0 + d_row,            q + growb);
    cp16(smem0 + 2560 * 4 + d_row, f + growb);
    asm volatile("cp.async.commit_group;" ::: "memory");
    float4 pk_ = *(const float4*)(k + growb);
    float4 pg  = *(const float4*)(g + growb);
    float4 cv, cg;
    if (colth) { cv = *(const float4*)(v + gcolb); cg = *(const float4*)(g + gcolb); }

    // state: 16 rows x 1 col = 8 packed f32x2
    u64 M[8];
#pragma unroll
    for (int p = 0; p < 8; p++) M[p] = 0ull;

    for (int ch = 0; ch < NC; ch++) {
        const float* bufqf = smp + (ch & 1) * 5120;
        // ---- stage kg, vg from regs (prev compute done per loop-end sync) ----
        {
            float4 kg;
            kg.x = pk_.x * pg.x; kg.y = pk_.y * pg.y;
            kg.z = pk_.z * pg.z; kg.w = pk_.w * pg.w;
            *(float4*)(smp + KG_OFF + rbidx) = kg;
            if (colth) {
                float4 vg;
                vg.x = cv.x * cg.x; vg.y = cv.y * cg.y;
                vg.z = cv.z * cg.z; vg.w = cv.w * cg.w;
                *(float4*)(smp + VG_OFF + c_s * 64 + c_cb * 4) = vg;
            }
        }
        asm volatile("cp.async.wait_group 0;" ::: "memory");
        __syncthreads();
        // ---- issue next chunk's loads (overlap with compute) ----
        if (ch + 1 < NC) {
            const long off = (long)(ch + 1) * S_ * HD;
            const uint32_t bq = smem0 + (uint32_t)(((ch + 1) & 1) * 5120) * 4;
            cp16(bq + d_row,            q + growb + off);
            cp16(bq + 2560 * 4 + d_row, f + growb + off);
            asm volatile("cp.async.commit_group;" ::: "memory");
            pk_ = *(const float4*)(k + growb + off);
            pg  = *(const float4*)(g + growb + off);
            if (colth) {
                cv = *(const float4*)(v + gcolb + off);
                cg = *(const float4*)(g + gcolb + off);
            }
        }
        // ---- compute 16 steps ----
#pragma unroll
        for (int s = 0; s < S_; s++) {
            const float* qb = bufqf + s * 160 + rl;
            const float* fb = bufqf + 2560 + s * 160 + rl;
            const float* kb = smp + KG_OFF + s * 160 + rl;
            const float fc  = bufqf[2560 + s * 160 + fcidx];
            const float vgc = smp[VG_OFF + s * 64 + vcidx];
            const u64 fj = pk2(fc, fc);
            const u64 vj = pk2(vgc, vgc);
            u64 oa = 0ull, ob = 0ull;
#pragma unroll
            for (int l = 0; l < 4; l++) {
                float4 f4 = *(const float4*)(fb + l * 4);
                float4 k4 = *(const float4*)(kb + l * 4);
                float4 q4 = *(const float4*)(qb + l * 4);
                u64 fo, wv;
                fo = max2c(mul2(pk2(f4.x, f4.y), fj), 0.8f);
                wv = mul2(pk2(k4.x, k4.y), vj);
                M[l * 2] = fma2(M[l * 2], fo, wv);
                oa = fma2(pk2(q4.x, q4.y), M[l * 2], oa);
                fo = max2c(mul2(pk2(f4.z, f4.w), fj), 0.8f);
                wv = mul2(pk2(k4.z, k4.w), vj);
                M[l * 2 + 1] = fma2(M[l * 2 + 1], fo, wv);
                ob = fma2(pk2(q4.z, q4.w), M[l * 2 + 1], ob);
            }
            const float2 oo = up2(add2(oa, ob));
            float osum = oo.x + oo.y;
            osum += __shfl_xor_sync(0xffffffffu, osum, 4);
            osum += __shfl_xor_sync(0xffffffffu, osum, 8);
            osum += __shfl_xor_sync(0xffffffffu, osum, 16);
            if (lane < 4) outp[s * HD] = osum;
        }
        outp += S_ * HD;
        __syncthreads();   // compute done before next staging overwrites kg/vg
    }
}

extern "C" void kernel_launch(void* const* d_in, const int* in_sizes, int n_in,
                              void* d_out, int out_size) {
    const float* q = (const float*)d_in[0];
    const float* k = (const float*)d_in[1];
    const float* v = (const float*)d_in[2];
    const float* f = (const float*)d_in[3];
    const float* g = (const float*)d_in[4];
    cudaFuncSetAttribute(delta_kernel,
                         cudaFuncAttributeMaxDynamicSharedMemorySize, SM_BYTES);
    dim3 grid(2, H_, B_);
    delta_kernel<<<grid, 512, SM_BYTES>>>(q, k, v, f, g, (float*)d_out);
}

// round 9
// speedup vs baseline: 1.6626x; 1.6626x over previous
#include <cuda_runtime.h>
#include <cuda_bf16.h>

#define B_ 4
#define T_ 2048
#define H_ 16
#define D_ 128
#define HD 2048        // H_*D_
#define S_ 16          // steps per chunk
#define NC (T_/S_)     // 128 chunks

typedef unsigned long long u64;

__device__ __forceinline__ u64 pk2(float x, float y) {
    u64 r; asm("mov.b64 %0,{%1,%2};" : "=l"(r) : "f"(x), "f"(y)); return r;
}
__device__ __forceinline__ float2 up2(u64 a) {
    float2 r; asm("mov.b64 {%0,%1},%2;" : "=f"(r.x), "=f"(r.y) : "l"(a)); return r;
}
__device__ __forceinline__ u64 mul2(u64 a, u64 b) {
    u64 d; asm("mul.rn.f32x2 %0,%1,%2;" : "=l"(d) : "l"(a), "l"(b)); return d;
}
__device__ __forceinline__ u64 add2(u64 a, u64 b) {
    u64 d; asm("add.rn.f32x2 %0,%1,%2;" : "=l"(d) : "l"(a), "l"(b)); return d;
}
__device__ __forceinline__ u64 fma2(u64 a, u64 b, u64 c) {
    u64 d; asm("fma.rn.f32x2 %0,%1,%2,%3;" : "=l"(d) : "l"(a), "l"(b), "l"(c)); return d;
}
__device__ __forceinline__ u64 max2c(u64 a, float c) {
    float2 t = up2(a);
    t.x = fmaxf(t.x, c); t.y = fmaxf(t.y, c);
    return pk2(t.x, t.y);
}

// One recurrence step for this thread's 16 rows x 1 column.
#define STEP(s) {                                                         \
    const float* fb = fsm + (s) * 160 + rl;                               \
    const float* kb = ksm + (s) * 160 + rl;                               \
    const float* qb = qsm + (s) * 160 + rl;                               \
    const float fc  = fsm[(s) * 160 + fcidx];                             \
    const float vgc = vgsm[(s) * 64 + vcidx];                             \
    const u64 fj = pk2(fc, fc);                                           \
    const u64 vj = pk2(vgc, vgc);                                         \
    u64 oa = 0ull, ob = 0ull;                                             \
    _Pragma("unroll")                                                     \
    for (int l = 0; l < 4; l++) {                                         \
        float4 f4 = *(const float4*)(fb + l * 4);                         \
        float4 k4 = *(const float4*)(kb + l * 4);                         \
        float4 q4 = *(const float4*)(qb + l * 4);                         \
        u64 fo, wv;                                                       \
        fo = max2c(mul2(pk2(f4.x, f4.y), fj), 0.8f);                      \
        wv = mul2(pk2(k4.x, k4.y), vj);                                   \
        M[l * 2] = fma2(M[l * 2], fo, wv);                                \
        oa = fma2(pk2(q4.x, q4.y), M[l * 2], oa);                         \
        fo = max2c(mul2(pk2(f4.z, f4.w), fj), 0.8f);                      \
        wv = mul2(pk2(k4.z, k4.w), vj);                                   \
        M[l * 2 + 1] = fma2(M[l * 2 + 1], fo, wv);                        \
        ob = fma2(pk2(q4.z, q4.w), M[l * 2 + 1], ob);                     \
    }                                                                     \
    const float2 oo = up2(add2(oa, ob));                                  \
    float osum = oo.x + oo.y;                                             \
    osum += __shfl_xor_sync(0xffffffffu, osum, 4);                        \
    osum += __shfl_xor_sync(0xffffffffu, osum, 8);                        \
    osum += __shfl_xor_sync(0xffffffffu, osum, 16);                       \
    if (lane < 4) outp[(s) * HD] = osum;                                  \
}

// Row-data smem layout per t: 8 blocks of (16 floats + 4 pad) = 160 floats (640B).
// Block-base banks: r*20 mod 32 = {0,20,8,28,16,4,24,12} -> conflict-free LDS.128.
__global__ __launch_bounds__(512, 1) void delta_kernel(
    const float* __restrict__ q, const float* __restrict__ k,
    const float* __restrict__ v, const float* __restrict__ f,
    const float* __restrict__ g, float* __restrict__ out)
{
    __shared__ float fsm[S_ * 160];
    __shared__ float ksm[S_ * 160];   // holds kg = k*g
    __shared__ float qsm[S_ * 160];
    __shared__ float vgsm[S_ * 64];   // vg = v*g for this CTA's 64 columns

    const int tid  = threadIdx.x;
    const int w    = tid >> 5, lane = tid & 31;
    const int r    = lane >> 2;          // 8 row-groups of 16 rows
    const int c    = lane & 3;           // 4 columns per warp
    const int colbase = blockIdx.x * 64;
    const long base0  = (long)blockIdx.z * T_ * HD + (long)blockIdx.y * D_;

    // staging roles
    const int  s_s = tid >> 5, s_rb = tid & 31;   // rows: (step, 4-row block)
    const int  c_s = tid >> 4, c_cb = tid & 15;   // cols: (step, 4-col block)
    const bool colth = (tid < 256);
    const long growb = base0 + (long)s_s * HD + s_rb * 4;
    const long gcolb = base0 + (long)c_s * HD + colbase + c_cb * 4;

    // prefetch chunk 0 into registers
    float4 pq  = *(const float4*)(q + growb);
    float4 pk_ = *(const float4*)(k + growb);
    float4 pg  = *(const float4*)(g + growb);
    float4 pf  = *(const float4*)(f + growb);
    float4 cv, cg;
    if (colth) { cv = *(const float4*)(v + gcolb); cg = *(const float4*)(g + gcolb); }

    // state: 16 rows x 1 col as 8 packed f32x2
    u64 M[8];
#pragma unroll
    for (int p = 0; p < 8; p++) M[p] = 0ull;

    const int rbidx  = s_s * 160 + (s_rb >> 2) * 20 + (s_rb & 3) * 4;  // staging write idx
    const int rl     = r * 20;                                          // compute read base
    const int cj     = colbase + w * 4 + c;                             // my column
    const int fcidx  = (cj >> 4) * 20 + (cj & 15);
    const int vcidx  = w * 4 + c;
    float* outp = out + base0 + cj;             // bumped by S_*HD per chunk

    for (int ch = 0; ch < NC; ch++) {
        __syncthreads();                       // smem free (prev chunk consumed)
        // ---- stage prefetched regs -> smem ----
        {
            float4 kg;
            kg.x = pk_.x * pg.x; kg.y = pk_.y * pg.y;
            kg.z = pk_.z * pg.z; kg.w = pk_.w * pg.w;
            *(float4*)(fsm + rbidx) = pf;
            *(float4*)(ksm + rbidx) = kg;
            *(float4*)(qsm + rbidx) = pq;
            if (colth) {
                float4 vg;
                vg.x = cv.x * cg.x; vg.y = cv.y * cg.y;
                vg.z = cv.z * cg.z; vg.w = cv.w * cg.w;
                *(float4*)(vgsm + c_s * 64 + c_cb * 4) = vg;
            }
        }
        __syncthreads();
        // ---- compute steps 0-3 with minimal register pressure ----
#pragma unroll
        for (int s = 0; s < 4; s++) STEP(s)
        // ---- prefetch next chunk (issued off the barrier-ramp hot spot;
        //      12 remaining steps ~1900cyc >> 600cyc DRAM latency) ----
        if (ch + 1 < NC) {
            long off = (long)(ch + 1) * S_ * HD;
            pq  = *(const float4*)(q + growb + off);
            pk_ = *(const float4*)(k + growb + off);
            pg  = *(const float4*)(g + growb + off);
            pf  = *(const float4*)(f + growb + off);
            if (colth) {
                cv = *(const float4*)(v + gcolb + off);
                cg = *(const float4*)(g + gcolb + off);
            }
        }
        // ---- compute steps 4-15 ----
#pragma unroll
        for (int s = 4; s < S_; s++) STEP(s)
        outp += S_ * HD;
    }
}

extern "C" void kernel_launch(void* const* d_in, const int* in_sizes, int n_in,
                              void* d_out, int out_size) {
    const float* q = (const float*)d_in[0];
    const float* k = (const float*)d_in[1];
    const float* v = (const float*)d_in[2];
    const float* f = (const float*)d_in[3];
    const float* g = (const float*)d_in[4];
    dim3 grid(2, H_, B_);
    delta_kernel<<<grid, 512>>>(q, k, v, f, g, (float*)d_out);
}

// round 10
// speedup vs baseline: 1.6688x; 1.0037x over previous
#include <cuda_runtime.h>
#include <cuda_bf16.h>

#define B_ 4
#define T_ 2048
#define H_ 16
#define D_ 128
#define HD 2048        // H_*D_
#define S_ 16          // steps per chunk
#define NC (T_/S_)     // 128 chunks

// dynamic smem (float offsets)
#define FS 0           // f rows:  16 t * 160
#define KS 2560        // kg rows
#define QS 5120        // q rows
#define VG 7680        // vg cols: 16 t * 64
#define PT 8704        // partials: 2 parity * (16 t * 64 col * 8 rowgroup)
#define PT_SZ 8192
#define SM_FLOATS 25088
#define SM_BYTES 100352

typedef unsigned long long u64;

__device__ __forceinline__ u64 pk2(float x, float y) {
    u64 r; asm("mov.b64 %0,{%1,%2};" : "=l"(r) : "f"(x), "f"(y)); return r;
}
__device__ __forceinline__ float2 up2(u64 a) {
    float2 r; asm("mov.b64 {%0,%1},%2;" : "=f"(r.x), "=f"(r.y) : "l"(a)); return r;
}
__device__ __forceinline__ u64 mul2(u64 a, u64 b) {
    u64 d; asm("mul.rn.f32x2 %0,%1,%2;" : "=l"(d) : "l"(a), "l"(b)); return d;
}
__device__ __forceinline__ u64 add2(u64 a, u64 b) {
    u64 d; asm("add.rn.f32x2 %0,%1,%2;" : "=l"(d) : "l"(a), "l"(b)); return d;
}
__device__ __forceinline__ u64 fma2(u64 a, u64 b, u64 c) {
    u64 d; asm("fma.rn.f32x2 %0,%1,%2,%3;" : "=l"(d) : "l"(a), "l"(b), "l"(c)); return d;
}
__device__ __forceinline__ u64 max2c(u64 a, float c) {
    float2 t = up2(a);
    t.x = fmaxf(t.x, c); t.y = fmaxf(t.y, c);
    return pk2(t.x, t.y);
}

// Row-data smem layout per t: 8 blocks of (16 floats + 4 pad) = 160 floats (640B).
// Block-base banks: r*20 mod 32 = {0,20,8,28,16,4,24,12} -> conflict-free LDS.128.
__global__ __launch_bounds__(512, 1) void delta_kernel(
    const float* __restrict__ q, const float* __restrict__ k,
    const float* __restrict__ v, const float* __restrict__ f,
    const float* __restrict__ g, float* __restrict__ out)
{
    extern __shared__ float smp[];

    const int tid  = threadIdx.x;
    const int w    = tid >> 5, lane = tid & 31;
    const int r    = lane >> 2;          // 8 row-groups of 16 rows
    const int c    = lane & 3;           // 4 columns per warp
    const int colbase = blockIdx.x * 64;
    const long base0  = (long)blockIdx.z * T_ * HD + (long)blockIdx.y * D_;

    // staging roles
    const int  s_s = tid >> 5, s_rb = tid & 31;   // rows: (step, 4-row block)
    const int  c_s = tid >> 4, c_cb = tid & 15;   // cols: (step, 4-col block)
    const bool colth = (tid < 256);
    const long growb = base0 + (long)s_s * HD + s_rb * 4;
    const long gcolb = base0 + (long)c_s * HD + colbase + c_cb * 4;

    // prefetch chunk 0 into registers
    float4 pq  = *(const float4*)(q + growb);
    float4 pk_ = *(const float4*)(k + growb);
    float4 pg  = *(const float4*)(g + growb);
    float4 pf  = *(const float4*)(f + growb);
    float4 cv, cg;
    if (colth) { cv = *(const float4*)(v + gcolb); cg = *(const float4*)(g + gcolb); }

    // state: 16 rows x 1 col as 8 packed f32x2
    u64 M[8];
#pragma unroll
    for (int p = 0; p < 8; p++) M[p] = 0ull;

    const int rbidx  = s_s * 160 + (s_rb >> 2) * 20 + (s_rb & 3) * 4;  // staging write idx
    const int rl     = r * 20;                                          // compute read base
    const int cj     = colbase + w * 4 + c;                             // my column
    const int fcidx  = (cj >> 4) * 20 + (cj & 15);
    const int vcidx  = w * 4 + c;
    // partial slot: [parity][s][col][rowgroup]; banks c*8+r distinct per warp
    const int pidx   = PT + vcidx * 8 + r;

    // reduce-pass constants: 2 outputs per thread per chunk
    const int o0s = tid >> 6,         o0c = tid & 63;          // idx = tid
    const int o1s = (tid + 512) >> 6, o1c = tid & 63;          // idx = tid+512

    for (int ch = 0; ch < NC; ch++) {
        const int par = ch & 1;
        __syncthreads();   // prev compute done: tiles free, partials[1-par] complete
        // ---- reduce prev chunk's partials -> gmem (overlaps staging/LDG) ----
        if (ch > 0) {
            const float* pb = smp + PT + (1 - par) * PT_SZ;
            const long obase = base0 + (long)(ch - 1) * S_ * HD + colbase;
            {
                const float* p = pb + o0s * 512 + o0c * 8;
                float4 a = *(const float4*)p;
                float4 b2 = *(const float4*)(p + 4);
                out[obase + (long)o0s * HD + o0c] =
                    ((a.x + a.y) + (a.z + a.w)) + ((b2.x + b2.y) + (b2.z + b2.w));
            }
            {
                const float* p = pb + o1s * 512 + o1c * 8;
                float4 a = *(const float4*)p;
                float4 b2 = *(const float4*)(p + 4);
                out[obase + (long)o1s * HD + o1c] =
                    ((a.x + a.y) + (a.z + a.w)) + ((b2.x + b2.y) + (b2.z + b2.w));
            }
        }
        // ---- stage prefetched regs -> smem tiles ----
        {
            float4 kg;
            kg.x = pk_.x * pg.x; kg.y = pk_.y * pg.y;
            kg.z = pk_.z * pg.z; kg.w = pk_.w * pg.w;
            *(float4*)(smp + FS + rbidx) = pf;
            *(float4*)(smp + KS + rbidx) = kg;
            *(float4*)(smp + QS + rbidx) = pq;
            if (colth) {
                float4 vg;
                vg.x = cv.x * cg.x; vg.y = cv.y * cg.y;
                vg.z = cv.z * cg.z; vg.w = cv.w * cg.w;
                *(float4*)(smp + VG + c_s * 64 + c_cb * 4) = vg;
            }
        }
        __syncthreads();
        // ---- prefetch next chunk (latency overlaps compute) ----
        if (ch + 1 < NC) {
            long off = (long)(ch + 1) * S_ * HD;
            pq  = *(const float4*)(q + growb + off);
            pk_ = *(const float4*)(k + growb + off);
            pg  = *(const float4*)(g + growb + off);
            pf  = *(const float4*)(f + growb + off);
            if (colth) {
                cv = *(const float4*)(v + gcolb + off);
                cg = *(const float4*)(g + gcolb + off);
            }
        }
        // ---- compute 16 steps; lane partial -> STS.32 (no cross-lane chain) ----
        float* pw = smp + pidx + par * PT_SZ;
#pragma unroll
        for (int s = 0; s < S_; s++) {
            const float* fb = smp + FS + s * 160 + rl;
            const float* kb = smp + KS + s * 160 + rl;
            const float* qb = smp + QS + s * 160 + rl;
            const float fc  = smp[FS + s * 160 + fcidx];
            const float vgc = smp[VG + s * 64 + vcidx];
            const u64 fj = pk2(fc, fc);
            const u64 vj = pk2(vgc, vgc);
            u64 oa = 0ull, ob = 0ull;
#pragma unroll
            for (int l = 0; l < 4; l++) {
                float4 f4 = *(const float4*)(fb + l * 4);
                float4 k4 = *(const float4*)(kb + l * 4);
                float4 q4 = *(const float4*)(qb + l * 4);
                u64 fo, wv;
                fo = max2c(mul2(pk2(f4.x, f4.y), fj), 0.8f);
                wv = mul2(pk2(k4.x, k4.y), vj);
                M[l * 2] = fma2(M[l * 2], fo, wv);
                oa = fma2(pk2(q4.x, q4.y), M[l * 2], oa);
                fo = max2c(mul2(pk2(f4.z, f4.w), fj), 0.8f);
                wv = mul2(pk2(k4.z, k4.w), vj);
                M[l * 2 + 1] = fma2(M[l * 2 + 1], fo, wv);
                ob = fma2(pk2(q4.z, q4.w), M[l * 2 + 1], ob);
            }
            const float2 oo = up2(add2(oa, ob));
            pw[s * 512] = oo.x + oo.y;
        }
    }
    // ---- drain: reduce final chunk's partials ----
    __syncthreads();
    {
        const float* pb = smp + PT + ((NC - 1) & 1) * PT_SZ;
        const long obase = base0 + (long)(NC - 1) * S_ * HD + colbase;
        {
            const float* p = pb + o0s * 512 + o0c * 8;
            float4 a = *(const float4*)p;
            float4 b2 = *(const float4*)(p + 4);
            out[obase + (long)o0s * HD + o0c] =
                ((a.x + a.y) + (a.z + a.w)) + ((b2.x + b2.y) + (b2.z + b2.w));
        }
        {
            const float* p = pb + o1s * 512 + o1c * 8;
            float4 a = *(const float4*)p;
            float4 b2 = *(const float4*)(p + 4);
            out[obase + (long)o1s * HD + o1c] =
                ((a.x + a.y) + (a.z + a.w)) + ((b2.x + b2.y) + (b2.z + b2.w));
        }
    }
}

extern "C" void kernel_launch(void* const* d_in, const int* in_sizes, int n_in,
                              void* d_out, int out_size) {
    const float* q = (const float*)d_in[0];
    const float* k = (const float*)d_in[1];
    const float* v = (const float*)d_in[2];
    const float* f = (const float*)d_in[3];
    const float* g = (const float*)d_in[4];
    cudaFuncSetAttribute(delta_kernel,
                         cudaFuncAttributeMaxDynamicSharedMemorySize, SM_BYTES);
    dim3 grid(2, H_, B_);
    delta_kernel<<<grid, 512, SM_BYTES>>>(q, k, v, f, g, (float*)d_out);
}

// round 12
// speedup vs baseline: 1.8830x; 1.1284x over previous
#include <cuda_runtime.h>

#define B_ 4
#define T_ 2048
#define H_ 16
#define D_ 128
#define HD 2048        // H_*D_
#define S_ 16          // steps per chunk
#define NC (T_/S_)     // 128 chunks

// smem float offsets
#define FS 0           // f rows:  16 t * 128
#define KS 2048        // kg rows
#define QS 4096        // q rows
#define FC 6144        // f cols: 16 t * 64
#define VG 7168        // vg cols
#define PT 8192        // partials: 2 parity * 16 s * (16 rp * 68 = 1088)
#define PT_PAR 17408   // 16 * 1088
#define SM_FLOATS (8192 + 2 * 17408)
#define SM_BYTES  (SM_FLOATS * 4)    // 172032

typedef unsigned long long u64;

__device__ __forceinline__ u64 pk2(float x, float y) {
    u64 r; asm("mov.b64 %0,{%1,%2};" : "=l"(r) : "f"(x), "f"(y)); return r;
}
__device__ __forceinline__ float2 up2(u64 a) {
    float2 r; asm("mov.b64 {%0,%1},%2;" : "=f"(r.x), "=f"(r.y) : "l"(a)); return r;
}
__device__ __forceinline__ u64 mul2(u64 a, u64 b) {
    u64 d; asm("mul.rn.f32x2 %0,%1,%2;" : "=l"(d) : "l"(a), "l"(b)); return d;
}
__device__ __forceinline__ u64 add2(u64 a, u64 b) {
    u64 d; asm("add.rn.f32x2 %0,%1,%2;" : "=l"(d) : "l"(a), "l"(b)); return d;
}
__device__ __forceinline__ u64 fma2(u64 a, u64 b, u64 c) {
    u64 d; asm("fma.rn.f32x2 %0,%1,%2,%3;" : "=l"(d) : "l"(a), "l"(b), "l"(c)); return d;
}
__device__ __forceinline__ u64 max2c(u64 a, float c) {
    float2 t = up2(a);
    t.x = fmaxf(t.x, c); t.y = fmaxf(t.y, c);
    return pk2(t.x, t.y);
}
__device__ __forceinline__ u64 shflx8(u64 x) {   // shfl_xor(8) of a packed pair
    unsigned lo, hi;
    asm("mov.b64 {%0,%1},%2;" : "=r"(lo), "=r"(hi) : "l"(x));
    lo = __shfl_xor_sync(0xffffffffu, lo, 8);
    hi = __shfl_xor_sync(0xffffffffu, hi, 8);
    u64 r; asm("mov.b64 %0,{%1,%2};" : "=l"(r) : "r"(lo), "r"(hi));
    return r;
}

// per-column piece of one step: updates 2 packed M chains, emits scalar col-partial
#define COLJ(fcj, vgj, m0, m1, ocj) {                                     \
    const u64 fj = pk2(fcj, fcj);                                         \
    const u64 vj = pk2(vgj, vgj);                                         \
    const u64 fo0 = max2c(mul2(fp0, fj), 0.8f);                           \
    const u64 fo1 = max2c(mul2(fp1, fj), 0.8f);                           \
    m0 = fma2(m0, fo0, mul2(kp0, vj));                                    \
    m1 = fma2(m1, fo1, mul2(kp1, vj));                                    \
    u64 op = mul2(qp0, m0);                                               \
    op = fma2(qp1, m1, op);                                               \
    const float2 oo = up2(op);                                            \
    ocj = oo.x + oo.y;                                                    \
}

__global__ __launch_bounds__(512, 1) void delta_kernel(
    const float* __restrict__ q, const float* __restrict__ k,
    const float* __restrict__ v, const float* __restrict__ f,
    const float* __restrict__ g, float* __restrict__ out)
{
    extern __shared__ float smp[];

    const int tid  = threadIdx.x;
    const int w    = tid >> 5, lane = tid & 31;
    const int rt   = w >> 1;            // 8 row-tiles of 16 rows
    const int ct   = w & 1;             // 2 col-tiles of 32 cols
    const int lr   = lane >> 3;         // 4 row-blocks of 4 rows
    const int lc   = lane & 7;          // 8 col-blocks of 4 cols
    const int colbase = blockIdx.x * 64;
    const long base0  = (long)blockIdx.z * T_ * HD + (long)blockIdx.y * D_;

    const int R0 = rt * 16 + lr * 4;    // my 4 rows
    const int C0 = ct * 32 + lc * 4;    // my 4 cols (local)
    const int rp68 = (rt * 2 + (lr >> 1)) * 68;   // partial row-part slot (16B aligned)
    const bool stsOK = ((lr & 1) == 0);

    // staging roles
    const int  s_s = tid >> 5, s_rb = tid & 31;   // rows: (t, 4-float granule)
    const int  c_s = tid >> 4, c_cb = tid & 15;   // cols: (t, 4-col block), tid<256
    const bool colth = (tid < 256);
    const long growb = base0 + (long)s_s * HD + s_rb * 4;
    const long gcolb = base0 + (long)c_s * HD + colbase + c_cb * 4;
    const int  rbidx = s_s * 128 + s_rb * 4;
    const int  cidx  = c_s * 64 + c_cb * 4;

    // prefetch chunk 0
    float4 pq  = *(const float4*)(q + growb);
    float4 pk_ = *(const float4*)(k + growb);
    float4 pg  = *(const float4*)(g + growb);
    float4 pf  = *(const float4*)(f + growb);
    float4 cv, cg2, cf;
    if (colth) {
        cv  = *(const float4*)(v + gcolb);
        cg2 = *(const float4*)(g + gcolb);
        cf  = *(const float4*)(f + gcolb);
    }

    // state: 4 rows x 4 cols = 8 packed f32x2 (pairs along rows)
    u64 M[8];
#pragma unroll
    for (int p = 0; p < 8; p++) M[p] = 0ull;

    for (int ch = 0; ch < NC; ch++) {
        const int par = ch & 1;
        __syncthreads();   // prev compute done: tiles free, partials[1-par] complete
        // ---- reduce prev chunk's partials -> gmem (overlaps staging) ----
        if (ch > 0 && colth) {
            const float* pb = smp + PT + (1 - par) * PT_PAR;
            const int s2 = tid >> 4, cg = tid & 15;
            const float* p = pb + s2 * 1088 + cg * 4;
            u64 a0 = 0ull, a1 = 0ull;
#pragma unroll
            for (int rp = 0; rp < 16; rp++) {
                const float4 x = *(const float4*)(p + rp * 68);
                a0 = add2(a0, pk2(x.x, x.y));
                a1 = add2(a1, pk2(x.z, x.w));
            }
            const float2 r0 = up2(a0), r1 = up2(a1);
            *(float4*)(out + base0 + (long)(ch - 1) * S_ * HD + (long)s2 * HD
                       + colbase + cg * 4) = make_float4(r0.x, r0.y, r1.x, r1.y);
        }
        // ---- stage prefetched regs -> smem tiles ----
        {
            float4 kg;
            kg.x = pk_.x * pg.x; kg.y = pk_.y * pg.y;
            kg.z = pk_.z * pg.z; kg.w = pk_.w * pg.w;
            *(float4*)(smp + FS + rbidx) = pf;
            *(float4*)(smp + KS + rbidx) = kg;
            *(float4*)(smp + QS + rbidx) = pq;
            if (colth) {
                float4 vg;
                vg.x = cv.x * cg2.x; vg.y = cv.y * cg2.y;
                vg.z = cv.z * cg2.z; vg.w = cv.w * cg2.w;
                *(float4*)(smp + VG + cidx) = vg;
                *(float4*)(smp + FC + cidx) = cf;
            }
        }
        __syncthreads();
        // ---- prefetch next chunk (latency overlaps compute) ----
        if (ch + 1 < NC) {
            const long off = (long)(ch + 1) * S_ * HD;
            pq  = *(const float4*)(q + growb + off);
            pk_ = *(const float4*)(k + growb + off);
            pg  = *(const float4*)(g + growb + off);
            pf  = *(const float4*)(f + growb + off);
            if (colth) {
                cv  = *(const float4*)(v + gcolb + off);
                cg2 = *(const float4*)(g + gcolb + off);
                cf  = *(const float4*)(f + gcolb + off);
            }
        }
        // ---- compute 16 steps ----
        float* pw = smp + PT + par * PT_PAR + rp68 + C0;
#pragma unroll
        for (int s = 0; s < S_; s++) {
            const float4 f4  = *(const float4*)(smp + FS + s * 128 + R0);
            const float4 k4  = *(const float4*)(smp + KS + s * 128 + R0);
            const float4 q4  = *(const float4*)(smp + QS + s * 128 + R0);
            const float4 fc4 = *(const float4*)(smp + FC + s * 64 + C0);
            const float4 vg4 = *(const float4*)(smp + VG + s * 64 + C0);
            const u64 fp0 = pk2(f4.x, f4.y), fp1 = pk2(f4.z, f4.w);
            const u64 kp0 = pk2(k4.x, k4.y), kp1 = pk2(k4.z, k4.w);
            const u64 qp0 = pk2(q4.x, q4.y), qp1 = pk2(q4.z, q4.w);
            float oc0, oc1, oc2, oc3;
            COLJ(fc4.x, vg4.x, M[0], M[1], oc0)
            COLJ(fc4.y, vg4.y, M[2], M[3], oc1)
            COLJ(fc4.z, vg4.z, M[4], M[5], oc2)
            COLJ(fc4.w, vg4.w, M[6], M[7], oc3)
            // one butterfly round over xor-8 partner (lr pairs 0/1 and 2/3)
            u64 oA = pk2(oc0, oc1), oB = pk2(oc2, oc3);
            oA = add2(oA, shflx8(oA));
            oB = add2(oB, shflx8(oB));
            if (stsOK) {
                const float2 A = up2(oA), Bv = up2(oB);
                *(float4*)(pw + s * 1088) = make_float4(A.x, A.y, Bv.x, Bv.y);
            }
        }
    }
    // ---- drain: reduce final chunk's partials ----
    __syncthreads();
    if (colth) {
        const float* pb = smp + PT + ((NC - 1) & 1) * PT_PAR;
        const int s2 = tid >> 4, cg = tid & 15;
        const float* p = pb + s2 * 1088 + cg * 4;
        u64 a0 = 0ull, a1 = 0ull;
#pragma unroll
        for (int rp = 0; rp < 16; rp++) {
            const float4 x = *(const float4*)(p + rp * 68);
            a0 = add2(a0, pk2(x.x, x.y));
            a1 = add2(a1, pk2(x.z, x.w));
        }
        const float2 r0 = up2(a0), r1 = up2(a1);
        *(float4*)(out + base0 + (long)(NC - 1) * S_ * HD + (long)s2 * HD
                   + colbase + cg * 4) = make_float4(r0.x, r0.y, r1.x, r1.y);
    }
}

extern "C" void kernel_launch(void* const* d_in, const int* in_sizes, int n_in,
                              void* d_out, int out_size) {
    const float* q = (const float*)d_in[0];
    const float* k = (const float*)d_in[1];
    const float* v = (const float*)d_in[2];
    const float* f = (const float*)d_in[3];
    const float* g = (const float*)d_in[4];
    cudaFuncSetAttribute(delta_kernel,
                         cudaFuncAttributeMaxDynamicSharedMemorySize, SM_BYTES);
    dim3 grid(2, H_, B_);
    delta_kernel<<<grid, 512, SM_BYTES>>>(q, k, v, f, g, (float*)d_out);
}